// round 9
// baseline (speedup 1.0000x reference)
#include <cuda_runtime.h>
#include <math.h>
#include <stdint.h>

#define NN 100000
#define EE 1600000
#define DHID 256
#define DOUT 40
#define NB_SCAN ((NN + 1023) / 1024)

// PDL device primitives (sm_90+ generic PTX)
#define PDL_TRIGGER() asm volatile("griddepcontrol.launch_dependents;")
#define PDL_WAIT()    asm volatile("griddepcontrol.wait;" ::: "memory")

// ---------------- scratch (device globals; zero-initialized at module load) ----------------
__device__ int   g_outdeg[NN];
__device__ int   g_indeg[NN];
__device__ float g_isout[NN];
__device__ float g_isin[NN];
__device__ int   g_rowptr[NN + 1];
__device__ int   g_fill[NN];
__device__ int   g_bsum[NB_SCAN + 1];
__device__ int   g_cols[EE];
__device__ float g_z[(size_t)NN * DHID];   // GEMM output
__device__ float g_h[(size_t)NN * DHID];   // SpMM output / next-layer input

// Counters (g_outdeg/g_indeg/g_fill) are zeroed AFTER their last use each
// replay (scan_final / spmm), so every replay starts clean.

// ---------------- graph prep ----------------
__global__ void degree_kernel(const int* __restrict__ src, const int* __restrict__ dst) {
    PDL_TRIGGER();                 // let scan_partial launch early
    int e = blockIdx.x * blockDim.x + threadIdx.x;
    if (e < EE) {
        atomicAdd(&g_outdeg[src[e]], 1);
        atomicAdd(&g_indeg[dst[e]], 1);
    }
}

__global__ void scan_partial_kernel() {
    PDL_TRIGGER();
    PDL_WAIT();                    // g_indeg from degree_kernel
    __shared__ int ws[32];
    const int b = blockIdx.x, tid = threadIdx.x;
    const int i = b * 1024 + tid;
    int x = (i < NN) ? g_indeg[i] : 0;
    #pragma unroll
    for (int off = 16; off > 0; off >>= 1) x += __shfl_down_sync(0xffffffffu, x, off);
    if ((tid & 31) == 0) ws[tid >> 5] = x;
    __syncthreads();
    if (tid < 32) {
        int w = ws[tid];
        #pragma unroll
        for (int off = 16; off > 0; off >>= 1) w += __shfl_down_sync(0xffffffffu, w, off);
        if (tid == 0) g_bsum[b] = w;
    }
}

__global__ void scan_mid_kernel() {
    PDL_TRIGGER();
    PDL_WAIT();                    // g_bsum from scan_partial
    if (threadIdx.x == 0) {
        int run = 0;
        for (int b = 0; b < NB_SCAN; b++) { int t = g_bsum[b]; g_bsum[b] = run; run += t; }
        g_rowptr[NN] = run;
    }
}

// rowptr + isout/isin, then zero degree counters for the next replay
__global__ void scan_final_kernel() {
    PDL_TRIGGER();
    PDL_WAIT();                    // g_bsum offsets from scan_mid
    __shared__ int ws[32];
    const int b = blockIdx.x, tid = threadIdx.x;
    const int lane = tid & 31, wid = tid >> 5;
    const int i = b * 1024 + tid;
    const int v = (i < NN) ? g_indeg[i] : 0;
    int x = v;
    #pragma unroll
    for (int off = 1; off < 32; off <<= 1) {
        int y = __shfl_up_sync(0xffffffffu, x, off);
        if (lane >= off) x += y;
    }
    if (lane == 31) ws[wid] = x;
    __syncthreads();
    if (wid == 0) {
        int w = ws[lane];
        #pragma unroll
        for (int off = 1; off < 32; off <<= 1) {
            int y = __shfl_up_sync(0xffffffffu, w, off);
            if (lane >= off) w += y;
        }
        ws[lane] = w;
    }
    __syncthreads();
    int incl = x + ((wid > 0) ? ws[wid - 1] : 0);
    if (i < NN) {
        g_rowptr[i] = g_bsum[b] + incl - v;
        int od = g_outdeg[i];
        g_isout[i] = (od > 0) ? rsqrtf((float)od) : 0.f;
        g_isin[i]  = (v > 0) ? rsqrtf((float)v) : 0.f;
        g_indeg[i]  = 0;
        g_outdeg[i] = 0;
    }
}

__global__ void csr_fill_kernel(const int* __restrict__ src, const int* __restrict__ dst) {
    PDL_WAIT();                    // g_rowptr from scan_final
    int e = blockIdx.x * blockDim.x + threadIdx.x;
    if (e < EE) {
        int d = dst[e];
        int p = g_rowptr[d] + atomicAdd(&g_fill[d], 1);
        g_cols[p] = src[e];
    }
}

// ---------------- GEMM: g_z[r,c] = sum_k A[r,k] * W[k,c]  (no row scaling) ----------------
// isout scaling is folded into the SpMM gather, so this kernel has no graph deps.
// Tile 128x128, BK=16, 256 threads, 8x8/thread via packed f32x2 FMA; Bd swizzled.
#define FMA2(d, a, b) asm("fma.rn.f32x2 %0, %1, %2, %0;" : "+l"(d) : "l"(a), "l"(b))

__global__ __launch_bounds__(256, 2)
void gemm_kernel(const float* __restrict__ Xin, int use_x,
                 const float* __restrict__ W, int nrows, int ncols)
{
    PDL_TRIGGER();                 // layer-1: lets the prep chain start immediately
    const float* __restrict__ A = use_x ? Xin : (const float*)g_h;
    __shared__ float As[16][128];                 // [k][m]
    __shared__ unsigned long long BdS[16][128];   // [k][swizzled pair slot]

    const int tid = threadIdx.x;
    const int tx = tid & 15, ty = tid >> 4;
    const int rowBase = blockIdx.y * 128;
    const int colBase = blockIdx.x * 128;

    const int lr = tid >> 1;
    const int lk = (tid & 1) * 8;
    const int arow = rowBase + lr;

    const int bk  = tid >> 4;
    const int btx = tid & 15;
    const int bc0 = colBase + btx * 8;

    unsigned long long acc[4][8];
    #pragma unroll
    for (int i = 0; i < 4; i++)
        #pragma unroll
        for (int j = 0; j < 8; j++) acc[i][j] = 0ull;

    for (int k0 = 0; k0 < 256; k0 += 16) {
        float4 a0 = make_float4(0.f, 0.f, 0.f, 0.f), a1 = a0;
        if (arow < nrows) {
            const float4* Ar = reinterpret_cast<const float4*>(A + (size_t)arow * 256);
            a0 = Ar[(k0 + lk) >> 2];
            a1 = Ar[(k0 + lk + 4) >> 2];
        }
        As[lk + 0][lr] = a0.x; As[lk + 1][lr] = a0.y;
        As[lk + 2][lr] = a0.z; As[lk + 3][lr] = a0.w;
        As[lk + 4][lr] = a1.x; As[lk + 5][lr] = a1.y;
        As[lk + 6][lr] = a1.z; As[lk + 7][lr] = a1.w;

        float bv[8];
        if (bc0 + 7 < ncols) {
            const float* Wr = &W[(size_t)(k0 + bk) * ncols + bc0];
            float4 w0 = *reinterpret_cast<const float4*>(Wr);
            float4 w1 = *reinterpret_cast<const float4*>(Wr + 4);
            bv[0] = w0.x; bv[1] = w0.y; bv[2] = w0.z; bv[3] = w0.w;
            bv[4] = w1.x; bv[5] = w1.y; bv[6] = w1.z; bv[7] = w1.w;
        } else {
            #pragma unroll
            for (int m = 0; m < 8; m++)
                bv[m] = (bc0 + m < ncols) ? W[(size_t)(k0 + bk) * ncols + bc0 + m] : 0.f;
        }
        #pragma unroll
        for (int m = 0; m < 8; m++) {
            unsigned int b = __float_as_uint(bv[m]);
            unsigned long long pv = ((unsigned long long)b << 32) | (unsigned long long)b;
            BdS[bk][m * 16 + btx] = pv;
        }
        __syncthreads();

        #pragma unroll
        for (int kk = 0; kk < 16; kk++) {
            unsigned long long a2[4], bd[8];
            #pragma unroll
            for (int i = 0; i < 4; i++)
                a2[i] = *reinterpret_cast<const unsigned long long*>(&As[kk][ty * 8 + 2 * i]);
            #pragma unroll
            for (int j = 0; j < 8; j++)
                bd[j] = BdS[kk][j * 16 + tx];
            #pragma unroll
            for (int i = 0; i < 4; i++)
                #pragma unroll
                for (int j = 0; j < 8; j++)
                    FMA2(acc[i][j], a2[i], bd[j]);
        }
        __syncthreads();
    }

    const int c0 = colBase + tx * 8;
    #pragma unroll
    for (int i = 0; i < 4; i++) {
        #pragma unroll
        for (int h = 0; h < 2; h++) {
            int r = rowBase + ty * 8 + 2 * i + h;
            if (r >= nrows) continue;
            float vals[8];
            #pragma unroll
            for (int j = 0; j < 8; j++) {
                unsigned long long p = acc[i][j];
                unsigned int bits = h ? (unsigned int)(p >> 32) : (unsigned int)p;
                vals[j] = __uint_as_float(bits);
            }
            if (c0 + 7 < ncols) {
                float* zr = &g_z[(size_t)r * ncols + c0];
                *reinterpret_cast<float4*>(zr)     = make_float4(vals[0], vals[1], vals[2], vals[3]);
                *reinterpret_cast<float4*>(zr + 4) = make_float4(vals[4], vals[5], vals[6], vals[7]);
            } else {
                #pragma unroll
                for (int j = 0; j < 8; j++)
                    if (c0 + j < ncols) g_z[(size_t)r * ncols + c0 + j] = vals[j];
            }
        }
    }
}

// ---------------- SpMM gather, feature-split, isout folded into the gather ----------------
// g_h[n, d] = relu(isin[n] * sum_e isout[src_e]*g_z[src_e, d] + b[d]); d = half*128+tid.
__global__ __launch_bounds__(128)
void spmm_half_kernel(const float* __restrict__ bias, int half)
{
    __shared__ int   scols[128];
    __shared__ float souts[128];
    const int n = blockIdx.x;
    const int tid = threadIdx.x;
    const int d = half * 128 + tid;
    const int beg = g_rowptr[n];
    const int deg = g_rowptr[n + 1] - beg;
    if (tid == 0) g_fill[n] = 0;   // reset CSR fill counter for next replay (idempotent)
    float acc = 0.f;

    for (int base = 0; base < deg; base += 128) {
        const int m = min(128, deg - base);
        if (tid < m) {
            int s = g_cols[beg + base + tid];
            scols[tid] = s;
            souts[tid] = g_isout[s];
        }
        __syncthreads();
        int j = 0;
        for (; j + 8 <= m; j += 8) {
            float v0 = __ldg(&g_z[(size_t)scols[j + 0] * 256 + d]);
            float v1 = __ldg(&g_z[(size_t)scols[j + 1] * 256 + d]);
            float v2 = __ldg(&g_z[(size_t)scols[j + 2] * 256 + d]);
            float v3 = __ldg(&g_z[(size_t)scols[j + 3] * 256 + d]);
            float v4 = __ldg(&g_z[(size_t)scols[j + 4] * 256 + d]);
            float v5 = __ldg(&g_z[(size_t)scols[j + 5] * 256 + d]);
            float v6 = __ldg(&g_z[(size_t)scols[j + 6] * 256 + d]);
            float v7 = __ldg(&g_z[(size_t)scols[j + 7] * 256 + d]);
            acc = fmaf(v0, souts[j + 0], acc);
            acc = fmaf(v1, souts[j + 1], acc);
            acc = fmaf(v2, souts[j + 2], acc);
            acc = fmaf(v3, souts[j + 3], acc);
            acc = fmaf(v4, souts[j + 4], acc);
            acc = fmaf(v5, souts[j + 5], acc);
            acc = fmaf(v6, souts[j + 6], acc);
            acc = fmaf(v7, souts[j + 7], acc);
        }
        for (; j < m; ++j)
            acc = fmaf(__ldg(&g_z[(size_t)scols[j] * 256 + d]), souts[j], acc);
        __syncthreads();
    }

    float v = fmaf(acc, g_isin[n], bias[d]);
    g_h[(size_t)n * 256 + d] = fmaxf(v, 0.f);
}

// ---------------- layer-3 SpMM (D=40, isout at gather) fused with log_softmax ----------------
__global__ __launch_bounds__(64)
void spmm_logsoftmax_kernel(const float* __restrict__ bias, float* __restrict__ out)
{
    const int n = blockIdx.x;
    const int d = threadIdx.x;   // 0..63, active d<40
    const int beg = g_rowptr[n];
    const int end = g_rowptr[n + 1];
    float acc = 0.f;
    if (d < DOUT) {
        for (int p = beg; p < end; ++p) {
            int s = __ldg(&g_cols[p]);
            acc = fmaf(__ldg(&g_isout[s]), __ldg(&g_z[(size_t)s * DOUT + d]), acc);
        }
    }
    float v = (d < DOUT) ? fmaf(acc, g_isin[n], bias[d]) : -INFINITY;

    __shared__ float sm[64];
    sm[d] = v;
    __syncthreads();
    #pragma unroll
    for (int off = 32; off > 0; off >>= 1) {
        if (d < off) sm[d] = fmaxf(sm[d], sm[d + off]);
        __syncthreads();
    }
    float mx = sm[0];
    __syncthreads();
    float ex = (d < DOUT) ? expf(v - mx) : 0.f;
    sm[d] = ex;
    __syncthreads();
    #pragma unroll
    for (int off = 32; off > 0; off >>= 1) {
        if (d < off) sm[d] += sm[d + off];
        __syncthreads();
    }
    float lse = mx + logf(sm[0]);
    if (d < DOUT) out[(size_t)n * DOUT + d] = v - lse;
}

// ---------------- host-side PDL launch helper ----------------
static void launch_pdl(const void* func, dim3 grid, dim3 block, void** args)
{
    cudaLaunchConfig_t cfg = {};
    cfg.gridDim = grid;
    cfg.blockDim = block;
    cfg.dynamicSmemBytes = 0;
    cfg.stream = 0;   // same default stream as <<<>>>
    cudaLaunchAttribute attr[1];
    attr[0].id = cudaLaunchAttributeProgrammaticStreamSerialization;
    attr[0].val.programmaticStreamSerializationAllowed = 1;
    cfg.attrs = attr;
    cfg.numAttrs = 1;
    cudaLaunchKernelExC(&cfg, func, args);
}

// ---------------- launch ----------------
extern "C" void kernel_launch(void* const* d_in, const int* in_sizes, int n_in,
                              void* d_out, int out_size)
{
    const float* x  = (const float*)d_in[0];
    const float* W1 = (const float*)d_in[1];
    const float* b1 = (const float*)d_in[2];
    const float* W2 = (const float*)d_in[3];
    const float* b2 = (const float*)d_in[4];
    const float* W3 = (const float*)d_in[5];
    const float* b3 = (const float*)d_in[6];
    const int*  src = (const int*)d_in[7];
    const int*  dst = (const int*)d_in[8];
    float* out = (float*)d_out;

    const int nb_e = (EE + 255) / 256;
    const int gm = (NN + 127) / 128;

    // Layer-1 GEMM first (no graph deps) — prep chain overlaps via PDL.
    gemm_kernel<<<dim3(2, gm), 256>>>(x, 1, W1, NN, 256);

    {
        void* a_deg[] = { (void*)&src, (void*)&dst };
        launch_pdl((const void*)degree_kernel, dim3(nb_e), dim3(256), a_deg);
        launch_pdl((const void*)scan_partial_kernel, dim3(NB_SCAN), dim3(1024), nullptr);
        launch_pdl((const void*)scan_mid_kernel, dim3(1), dim3(32), nullptr);
        launch_pdl((const void*)scan_final_kernel, dim3(NB_SCAN), dim3(1024), nullptr);
        void* a_csr[] = { (void*)&src, (void*)&dst };
        launch_pdl((const void*)csr_fill_kernel, dim3(nb_e), dim3(256), a_csr);
    }

    // SpMM1 (normal launch: joins GEMM1 + prep chain)
    spmm_half_kernel<<<NN, 128>>>(b1, 0);
    spmm_half_kernel<<<NN, 128>>>(b1, 1);

    // layer 2
    gemm_kernel<<<dim3(2, gm), 256>>>(x, 0, W2, NN, 256);
    spmm_half_kernel<<<NN, 128>>>(b2, 0);
    spmm_half_kernel<<<NN, 128>>>(b2, 1);

    // layer 3 (D_OUT=40) + log_softmax
    gemm_kernel<<<dim3(1, gm), 256>>>(x, 0, W3, NN, 40);
    spmm_logsoftmax_kernel<<<NN, 64>>>(b3, out);
}

// round 10
// speedup vs baseline: 1.0551x; 1.0551x over previous
#include <cuda_runtime.h>
#include <math.h>
#include <stdint.h>

#define NN 100000
#define EE 1600000
#define DHID 256
#define DOUT 40
#define NB_SCAN ((NN + 1023) / 1024)

// ---------------- scratch (device globals; zero-initialized at module load) ----------------
__device__ int   g_outdeg[NN];
__device__ int   g_indeg[NN];
__device__ float g_isout[NN];
__device__ float g_isin[NN];
__device__ int   g_rowptr[NN + 1];
__device__ int   g_fill[NN];
__device__ int   g_bsum[NB_SCAN + 1];
__device__ int   g_cols[EE];
__device__ float g_z[(size_t)NN * DHID];   // GEMM output
__device__ float g_h[(size_t)NN * DHID];   // SpMM output / next-layer input

// Counters (g_outdeg/g_indeg/g_fill) are zeroed AFTER their last use each
// replay (scan_final / spmm), so every replay starts clean.

// ---------------- graph prep ----------------
__global__ void degree_kernel(const int* __restrict__ src, const int* __restrict__ dst) {
    int e = blockIdx.x * blockDim.x + threadIdx.x;
    if (e < EE) {
        atomicAdd(&g_outdeg[src[e]], 1);
        atomicAdd(&g_indeg[dst[e]], 1);
    }
}

__global__ void scan_partial_kernel() {
    __shared__ int ws[32];
    const int b = blockIdx.x, tid = threadIdx.x;
    const int i = b * 1024 + tid;
    int x = (i < NN) ? g_indeg[i] : 0;
    #pragma unroll
    for (int off = 16; off > 0; off >>= 1) x += __shfl_down_sync(0xffffffffu, x, off);
    if ((tid & 31) == 0) ws[tid >> 5] = x;
    __syncthreads();
    if (tid < 32) {
        int w = ws[tid];
        #pragma unroll
        for (int off = 16; off > 0; off >>= 1) w += __shfl_down_sync(0xffffffffu, w, off);
        if (tid == 0) g_bsum[b] = w;
    }
}

__global__ void scan_mid_kernel() {
    if (threadIdx.x == 0) {
        int run = 0;
        for (int b = 0; b < NB_SCAN; b++) { int t = g_bsum[b]; g_bsum[b] = run; run += t; }
        g_rowptr[NN] = run;
    }
}

// rowptr + isout/isin, then zero degree counters for the next replay
__global__ void scan_final_kernel() {
    __shared__ int ws[32];
    const int b = blockIdx.x, tid = threadIdx.x;
    const int lane = tid & 31, wid = tid >> 5;
    const int i = b * 1024 + tid;
    const int v = (i < NN) ? g_indeg[i] : 0;
    int x = v;
    #pragma unroll
    for (int off = 1; off < 32; off <<= 1) {
        int y = __shfl_up_sync(0xffffffffu, x, off);
        if (lane >= off) x += y;
    }
    if (lane == 31) ws[wid] = x;
    __syncthreads();
    if (wid == 0) {
        int w = ws[lane];
        #pragma unroll
        for (int off = 1; off < 32; off <<= 1) {
            int y = __shfl_up_sync(0xffffffffu, w, off);
            if (lane >= off) w += y;
        }
        ws[lane] = w;
    }
    __syncthreads();
    int incl = x + ((wid > 0) ? ws[wid - 1] : 0);
    if (i < NN) {
        g_rowptr[i] = g_bsum[b] + incl - v;
        int od = g_outdeg[i];
        g_isout[i] = (od > 0) ? rsqrtf((float)od) : 0.f;
        g_isin[i]  = (v > 0) ? rsqrtf((float)v) : 0.f;
        g_indeg[i]  = 0;
        g_outdeg[i] = 0;
    }
}

__global__ void csr_fill_kernel(const int* __restrict__ src, const int* __restrict__ dst) {
    int e = blockIdx.x * blockDim.x + threadIdx.x;
    if (e < EE) {
        int d = dst[e];
        int p = g_rowptr[d] + atomicAdd(&g_fill[d], 1);
        g_cols[p] = src[e];
    }
}

// ---------------- GEMM: g_z[r,c] = sum_k (A[r,k]*isout[r]) * W[k,c] ----------------
// Tile 128x128, BK=16, 256 threads, 8x8/thread via packed f32x2 FMA.
// Bd stores duplicated (b,b) pairs SWIZZLED (pair p at slot (p&7)*16 + (p>>3)):
// thread tx reads its 8 pairs at slot j*16+tx -> conflict-free.
// Grid is (colBlocks, rowBlocks): column-blocks sharing A rows dispatch
// adjacently -> second A read hits L2.
#define FMA2(d, a, b) asm("fma.rn.f32x2 %0, %1, %2, %0;" : "+l"(d) : "l"(a), "l"(b))

__global__ __launch_bounds__(256, 2)
void gemm_kernel(const float* __restrict__ Xin, int use_x,
                 const float* __restrict__ W, int nrows, int ncols)
{
    const float* __restrict__ A = use_x ? Xin : (const float*)g_h;
    __shared__ float As[16][128];                 // [k][m]
    __shared__ unsigned long long BdS[16][128];   // [k][swizzled pair slot]

    const int tid = threadIdx.x;
    const int tx = tid & 15, ty = tid >> 4;
    const int rowBase = blockIdx.y * 128;
    const int colBase = blockIdx.x * 128;

    const int lr = tid >> 1;
    const int lk = (tid & 1) * 8;
    const int arow = rowBase + lr;
    const float sc = (arow < nrows) ? g_isout[arow] : 0.f;

    const int bk  = tid >> 4;
    const int btx = tid & 15;
    const int bc0 = colBase + btx * 8;

    unsigned long long acc[4][8];
    #pragma unroll
    for (int i = 0; i < 4; i++)
        #pragma unroll
        for (int j = 0; j < 8; j++) acc[i][j] = 0ull;

    for (int k0 = 0; k0 < 256; k0 += 16) {
        float4 a0 = make_float4(0.f, 0.f, 0.f, 0.f), a1 = a0;
        if (arow < nrows) {
            const float4* Ar = reinterpret_cast<const float4*>(A + (size_t)arow * 256);
            a0 = Ar[(k0 + lk) >> 2];
            a1 = Ar[(k0 + lk + 4) >> 2];
        }
        As[lk + 0][lr] = a0.x * sc; As[lk + 1][lr] = a0.y * sc;
        As[lk + 2][lr] = a0.z * sc; As[lk + 3][lr] = a0.w * sc;
        As[lk + 4][lr] = a1.x * sc; As[lk + 5][lr] = a1.y * sc;
        As[lk + 6][lr] = a1.z * sc; As[lk + 7][lr] = a1.w * sc;

        float bv[8];
        {
            const float* Wr = &W[(size_t)(k0 + bk) * ncols + bc0];
            float4 w0 = *reinterpret_cast<const float4*>(Wr);
            float4 w1 = *reinterpret_cast<const float4*>(Wr + 4);
            bv[0] = w0.x; bv[1] = w0.y; bv[2] = w0.z; bv[3] = w0.w;
            bv[4] = w1.x; bv[5] = w1.y; bv[6] = w1.z; bv[7] = w1.w;
        }
        #pragma unroll
        for (int m = 0; m < 8; m++) {
            unsigned int b = __float_as_uint(bv[m]);
            unsigned long long pv = ((unsigned long long)b << 32) | (unsigned long long)b;
            BdS[bk][m * 16 + btx] = pv;
        }
        __syncthreads();

        #pragma unroll
        for (int kk = 0; kk < 16; kk++) {
            unsigned long long a2[4], bd[8];
            #pragma unroll
            for (int i = 0; i < 4; i++)
                a2[i] = *reinterpret_cast<const unsigned long long*>(&As[kk][ty * 8 + 2 * i]);
            #pragma unroll
            for (int j = 0; j < 8; j++)
                bd[j] = BdS[kk][j * 16 + tx];
            #pragma unroll
            for (int i = 0; i < 4; i++)
                #pragma unroll
                for (int j = 0; j < 8; j++)
                    FMA2(acc[i][j], a2[i], bd[j]);
        }
        __syncthreads();
    }

    const int c0 = colBase + tx * 8;
    #pragma unroll
    for (int i = 0; i < 4; i++) {
        #pragma unroll
        for (int h = 0; h < 2; h++) {
            int r = rowBase + ty * 8 + 2 * i + h;
            if (r >= nrows) continue;
            float vals[8];
            #pragma unroll
            for (int j = 0; j < 8; j++) {
                unsigned long long p = acc[i][j];
                unsigned int bits = h ? (unsigned int)(p >> 32) : (unsigned int)p;
                vals[j] = __uint_as_float(bits);
            }
            float* zr = &g_z[(size_t)r * ncols + c0];
            *reinterpret_cast<float4*>(zr)     = make_float4(vals[0], vals[1], vals[2], vals[3]);
            *reinterpret_cast<float4*>(zr + 4) = make_float4(vals[4], vals[5], vals[6], vals[7]);
        }
    }
}

// ---------------- narrow GEMM for layer 3: ncols=40, BN=64 tile, 128 threads ----------------
// Same scheme as gemm_kernel with 64 column slots: tx in 0..7, ty in 0..15.
// Bd swizzle: pair p at slot (p&7)*8 + (p>>3); read BdS[kk][j*8+tx] -> banks 2tx
// (8 distinct even bank-pairs; 4 ty-lanes broadcast). A reads: 4 distinct u64 (ty*32B).
__global__ __launch_bounds__(128, 4)
void gemm64_kernel(const float* __restrict__ W, int nrows, int ncols)
{
    const float* __restrict__ A = (const float*)g_h;
    __shared__ float As[16][128];
    __shared__ unsigned long long BdS[16][64];

    const int tid = threadIdx.x;
    const int tx = tid & 7, ty = tid >> 3;
    const int rowBase = blockIdx.x * 128;

    // A loader: 1 thread per row, 16 floats (4 x float4)
    const int lr = tid;
    const int arow = rowBase + lr;
    const float sc = (arow < nrows) ? g_isout[arow] : 0.f;

    // B loader: thread (bk, btx) loads 8 cols [btx*8 .. btx*8+7] of row bk
    const int bk  = tid >> 3;
    const int btx = tid & 7;
    const int bc0 = btx * 8;

    unsigned long long acc[4][8];
    #pragma unroll
    for (int i = 0; i < 4; i++)
        #pragma unroll
        for (int j = 0; j < 8; j++) acc[i][j] = 0ull;

    for (int k0 = 0; k0 < 256; k0 += 16) {
        // A tile
        if (arow < nrows) {
            const float4* Ar = reinterpret_cast<const float4*>(A + (size_t)arow * 256);
            #pragma unroll
            for (int q = 0; q < 4; q++) {
                float4 a = Ar[(k0 >> 2) + q];
                As[q * 4 + 0][lr] = a.x * sc;
                As[q * 4 + 1][lr] = a.y * sc;
                As[q * 4 + 2][lr] = a.z * sc;
                As[q * 4 + 3][lr] = a.w * sc;
            }
        } else {
            #pragma unroll
            for (int q = 0; q < 16; q++) As[q][lr] = 0.f;
        }
        // B tile (cols beyond ncols zero-padded)
        float bv[8];
        #pragma unroll
        for (int m = 0; m < 8; m++)
            bv[m] = (bc0 + m < ncols) ? W[(size_t)(k0 + bk) * ncols + bc0 + m] : 0.f;
        #pragma unroll
        for (int m = 0; m < 8; m++) {
            unsigned int b = __float_as_uint(bv[m]);
            BdS[bk][m * 8 + btx] = ((unsigned long long)b << 32) | (unsigned long long)b;
        }
        __syncthreads();

        #pragma unroll
        for (int kk = 0; kk < 16; kk++) {
            unsigned long long a2[4], bd[8];
            #pragma unroll
            for (int i = 0; i < 4; i++)
                a2[i] = *reinterpret_cast<const unsigned long long*>(&As[kk][ty * 8 + 2 * i]);
            #pragma unroll
            for (int j = 0; j < 8; j++)
                bd[j] = BdS[kk][j * 8 + tx];
            #pragma unroll
            for (int i = 0; i < 4; i++)
                #pragma unroll
                for (int j = 0; j < 8; j++)
                    FMA2(acc[i][j], a2[i], bd[j]);
        }
        __syncthreads();
    }

    const int c0 = tx * 8;
    #pragma unroll
    for (int i = 0; i < 4; i++) {
        #pragma unroll
        for (int h = 0; h < 2; h++) {
            int r = rowBase + ty * 8 + 2 * i + h;
            if (r >= nrows) continue;
            #pragma unroll
            for (int j = 0; j < 8; j++) {
                if (c0 + j < ncols) {
                    unsigned long long p = acc[i][j];
                    unsigned int bits = h ? (unsigned int)(p >> 32) : (unsigned int)p;
                    g_z[(size_t)r * ncols + c0 + j] = __uint_as_float(bits);
                }
            }
        }
    }
}

// ---------------- SpMM gather, feature-split: covers 128 of 256 dims per launch ----------------
__global__ __launch_bounds__(128)
void spmm_half_kernel(const float* __restrict__ bias, int half)
{
    __shared__ int scols[128];
    const int n = blockIdx.x;
    const int tid = threadIdx.x;
    const int d = half * 128 + tid;
    const int beg = g_rowptr[n];
    const int deg = g_rowptr[n + 1] - beg;
    if (tid == 0) g_fill[n] = 0;   // reset CSR fill counter for next replay
    float acc = 0.f;

    for (int base = 0; base < deg; base += 128) {
        const int m = min(128, deg - base);
        if (tid < m) scols[tid] = g_cols[beg + base + tid];
        __syncthreads();
        int j = 0;
        for (; j + 8 <= m; j += 8) {
            float v0 = __ldg(&g_z[(size_t)scols[j + 0] * 256 + d]);
            float v1 = __ldg(&g_z[(size_t)scols[j + 1] * 256 + d]);
            float v2 = __ldg(&g_z[(size_t)scols[j + 2] * 256 + d]);
            float v3 = __ldg(&g_z[(size_t)scols[j + 3] * 256 + d]);
            float v4 = __ldg(&g_z[(size_t)scols[j + 4] * 256 + d]);
            float v5 = __ldg(&g_z[(size_t)scols[j + 5] * 256 + d]);
            float v6 = __ldg(&g_z[(size_t)scols[j + 6] * 256 + d]);
            float v7 = __ldg(&g_z[(size_t)scols[j + 7] * 256 + d]);
            acc += ((v0 + v1) + (v2 + v3)) + ((v4 + v5) + (v6 + v7));
        }
        for (; j < m; ++j)
            acc += __ldg(&g_z[(size_t)scols[j] * 256 + d]);
        __syncthreads();
    }

    float v = fmaf(acc, g_isin[n], bias[d]);
    g_h[(size_t)n * 256 + d] = fmaxf(v, 0.f);
}

// ---------------- layer-3 SpMM (D=40) fused with log_softmax ----------------
__global__ __launch_bounds__(64)
void spmm_logsoftmax_kernel(const float* __restrict__ bias, float* __restrict__ out)
{
    const int n = blockIdx.x;
    const int d = threadIdx.x;   // 0..63, active d<40
    const int beg = g_rowptr[n];
    const int end = g_rowptr[n + 1];
    float acc = 0.f;
    if (d < DOUT) {
        int p = beg;
        for (; p + 4 <= end; p += 4) {
            float v0 = __ldg(&g_z[(size_t)__ldg(&g_cols[p + 0]) * DOUT + d]);
            float v1 = __ldg(&g_z[(size_t)__ldg(&g_cols[p + 1]) * DOUT + d]);
            float v2 = __ldg(&g_z[(size_t)__ldg(&g_cols[p + 2]) * DOUT + d]);
            float v3 = __ldg(&g_z[(size_t)__ldg(&g_cols[p + 3]) * DOUT + d]);
            acc += (v0 + v1) + (v2 + v3);
        }
        for (; p < end; ++p)
            acc += __ldg(&g_z[(size_t)__ldg(&g_cols[p]) * DOUT + d]);
    }
    float v = (d < DOUT) ? fmaf(acc, g_isin[n], bias[d]) : -INFINITY;

    __shared__ float sm[64];
    sm[d] = v;
    __syncthreads();
    #pragma unroll
    for (int off = 32; off > 0; off >>= 1) {
        if (d < off) sm[d] = fmaxf(sm[d], sm[d + off]);
        __syncthreads();
    }
    float mx = sm[0];
    __syncthreads();
    float ex = (d < DOUT) ? expf(v - mx) : 0.f;
    sm[d] = ex;
    __syncthreads();
    #pragma unroll
    for (int off = 32; off > 0; off >>= 1) {
        if (d < off) sm[d] += sm[d + off];
        __syncthreads();
    }
    float lse = mx + logf(sm[0]);
    if (d < DOUT) out[(size_t)n * DOUT + d] = v - lse;
}

// ---------------- launch ----------------
extern "C" void kernel_launch(void* const* d_in, const int* in_sizes, int n_in,
                              void* d_out, int out_size)
{
    const float* x  = (const float*)d_in[0];
    const float* W1 = (const float*)d_in[1];
    const float* b1 = (const float*)d_in[2];
    const float* W2 = (const float*)d_in[3];
    const float* b2 = (const float*)d_in[4];
    const float* W3 = (const float*)d_in[5];
    const float* b3 = (const float*)d_in[6];
    const int*  src = (const int*)d_in[7];
    const int*  dst = (const int*)d_in[8];
    float* out = (float*)d_out;

    const int nb_e = (EE + 255) / 256;
    const int gm = (NN + 127) / 128;

    // graph prep
    degree_kernel<<<nb_e, 256>>>(src, dst);
    scan_partial_kernel<<<NB_SCAN, 1024>>>();
    scan_mid_kernel<<<1, 32>>>();
    scan_final_kernel<<<NB_SCAN, 1024>>>();   // rowptr + isout/isin + counter reset
    csr_fill_kernel<<<nb_e, 256>>>(src, dst);

    // layer 1: z = (x*isout)@W1 ; h = relu(isin*gather(z) + b1)
    gemm_kernel<<<dim3(2, gm), 256>>>(x, 1, W1, NN, 256);
    spmm_half_kernel<<<NN, 128>>>(b1, 0);
    spmm_half_kernel<<<NN, 128>>>(b1, 1);

    // layer 2
    gemm_kernel<<<dim3(2, gm), 256>>>(x, 0, W2, NN, 256);
    spmm_half_kernel<<<NN, 128>>>(b2, 0);
    spmm_half_kernel<<<NN, 128>>>(b2, 1);

    // layer 3 (D_OUT=40, narrow tile) + log_softmax
    gemm64_kernel<<<gm, 128>>>(W3, NN, DOUT);
    spmm_logsoftmax_kernel<<<NN, 64>>>(b3, out);
}

// round 11
// speedup vs baseline: 1.2660x; 1.1998x over previous
#include <cuda_runtime.h>
#include <math.h>
#include <stdint.h>

#define NN 100000
#define EE 1600000
#define DHID 256
#define DOUT 40
#define NB_SCAN ((NN + 1023) / 1024)

// ---------------- scratch (device globals; zero-initialized at module load) ----------------
__device__ int   g_outdeg[NN];
__device__ int   g_indeg[NN];
__device__ float g_isout[NN];
__device__ float g_isin[NN];
__device__ int   g_rowptr[NN + 1];
__device__ int   g_fill[NN];
__device__ int   g_bsum[NB_SCAN + 1];
__device__ int   g_cols[EE];
__device__ float g_z[(size_t)NN * DHID];   // GEMM output
__device__ float g_h[(size_t)NN * DHID];   // SpMM output / next-layer input

// Counters (g_outdeg/g_indeg/g_fill) are zeroed AFTER their last use each
// replay (scan_final / spmm), so every replay starts clean.

// ---------------- graph prep ----------------
__global__ void degree_kernel(const int* __restrict__ src, const int* __restrict__ dst) {
    int e = blockIdx.x * blockDim.x + threadIdx.x;
    if (e < EE) {
        atomicAdd(&g_outdeg[src[e]], 1);
        atomicAdd(&g_indeg[dst[e]], 1);
    }
}

__global__ void scan_partial_kernel() {
    __shared__ int ws[32];
    const int b = blockIdx.x, tid = threadIdx.x;
    const int i = b * 1024 + tid;
    int x = (i < NN) ? g_indeg[i] : 0;
    #pragma unroll
    for (int off = 16; off > 0; off >>= 1) x += __shfl_down_sync(0xffffffffu, x, off);
    if ((tid & 31) == 0) ws[tid >> 5] = x;
    __syncthreads();
    if (tid < 32) {
        int w = ws[tid];
        #pragma unroll
        for (int off = 16; off > 0; off >>= 1) w += __shfl_down_sync(0xffffffffu, w, off);
        if (tid == 0) g_bsum[b] = w;
    }
}

__global__ void scan_mid_kernel() {
    if (threadIdx.x == 0) {
        int run = 0;
        for (int b = 0; b < NB_SCAN; b++) { int t = g_bsum[b]; g_bsum[b] = run; run += t; }
        g_rowptr[NN] = run;
    }
}

// rowptr + isout/isin, then zero degree counters for the next replay
__global__ void scan_final_kernel() {
    __shared__ int ws[32];
    const int b = blockIdx.x, tid = threadIdx.x;
    const int lane = tid & 31, wid = tid >> 5;
    const int i = b * 1024 + tid;
    const int v = (i < NN) ? g_indeg[i] : 0;
    int x = v;
    #pragma unroll
    for (int off = 1; off < 32; off <<= 1) {
        int y = __shfl_up_sync(0xffffffffu, x, off);
        if (lane >= off) x += y;
    }
    if (lane == 31) ws[wid] = x;
    __syncthreads();
    if (wid == 0) {
        int w = ws[lane];
        #pragma unroll
        for (int off = 1; off < 32; off <<= 1) {
            int y = __shfl_up_sync(0xffffffffu, w, off);
            if (lane >= off) w += y;
        }
        ws[lane] = w;
    }
    __syncthreads();
    int incl = x + ((wid > 0) ? ws[wid - 1] : 0);
    if (i < NN) {
        g_rowptr[i] = g_bsum[b] + incl - v;
        int od = g_outdeg[i];
        g_isout[i] = (od > 0) ? rsqrtf((float)od) : 0.f;
        g_isin[i]  = (v > 0) ? rsqrtf((float)v) : 0.f;
        g_indeg[i]  = 0;
        g_outdeg[i] = 0;
    }
}

__global__ void csr_fill_kernel(const int* __restrict__ src, const int* __restrict__ dst) {
    int e = blockIdx.x * blockDim.x + threadIdx.x;
    if (e < EE) {
        int d = dst[e];
        int p = g_rowptr[d] + atomicAdd(&g_fill[d], 1);
        g_cols[p] = src[e];
    }
}

// ---------------- GEMM: g_z[r,c] = sum_k (A[r,k]*isout[r]) * W[k,c] ----------------
// Tile 128x128, BK=16, 256 threads, 8x8/thread via packed f32x2 FMA.
// Bd stores duplicated (b,b) pairs SWIZZLED (pair p at slot (p&7)*16 + (p>>3)):
// thread tx reads its 8 pairs at slot j*16+tx -> conflict-free.
#define FMA2(d, a, b) asm("fma.rn.f32x2 %0, %1, %2, %0;" : "+l"(d) : "l"(a), "l"(b))

__global__ __launch_bounds__(256, 2)
void gemm_kernel(const float* __restrict__ Xin, int use_x,
                 const float* __restrict__ W, int nrows, int ncols)
{
    const float* __restrict__ A = use_x ? Xin : (const float*)g_h;
    __shared__ float As[16][128];                 // [k][m]
    __shared__ unsigned long long BdS[16][128];   // [k][swizzled pair slot]

    const int tid = threadIdx.x;
    const int tx = tid & 15, ty = tid >> 4;
    const int rowBase = blockIdx.y * 128;
    const int colBase = blockIdx.x * 128;

    const int lr = tid >> 1;
    const int lk = (tid & 1) * 8;
    const int arow = rowBase + lr;
    const float sc = (arow < nrows) ? g_isout[arow] : 0.f;

    const int bk  = tid >> 4;
    const int btx = tid & 15;
    const int bc0 = colBase + btx * 8;

    unsigned long long acc[4][8];
    #pragma unroll
    for (int i = 0; i < 4; i++)
        #pragma unroll
        for (int j = 0; j < 8; j++) acc[i][j] = 0ull;

    for (int k0 = 0; k0 < 256; k0 += 16) {
        float4 a0 = make_float4(0.f, 0.f, 0.f, 0.f), a1 = a0;
        if (arow < nrows) {
            const float4* Ar = reinterpret_cast<const float4*>(A + (size_t)arow * 256);
            a0 = Ar[(k0 + lk) >> 2];
            a1 = Ar[(k0 + lk + 4) >> 2];
        }
        As[lk + 0][lr] = a0.x * sc; As[lk + 1][lr] = a0.y * sc;
        As[lk + 2][lr] = a0.z * sc; As[lk + 3][lr] = a0.w * sc;
        As[lk + 4][lr] = a1.x * sc; As[lk + 5][lr] = a1.y * sc;
        As[lk + 6][lr] = a1.z * sc; As[lk + 7][lr] = a1.w * sc;

        float bv[8];
        {
            const float* Wr = &W[(size_t)(k0 + bk) * ncols + bc0];
            float4 w0 = *reinterpret_cast<const float4*>(Wr);
            float4 w1 = *reinterpret_cast<const float4*>(Wr + 4);
            bv[0] = w0.x; bv[1] = w0.y; bv[2] = w0.z; bv[3] = w0.w;
            bv[4] = w1.x; bv[5] = w1.y; bv[6] = w1.z; bv[7] = w1.w;
        }
        #pragma unroll
        for (int m = 0; m < 8; m++) {
            unsigned int b = __float_as_uint(bv[m]);
            unsigned long long pv = ((unsigned long long)b << 32) | (unsigned long long)b;
            BdS[bk][m * 16 + btx] = pv;
        }
        __syncthreads();

        #pragma unroll
        for (int kk = 0; kk < 16; kk++) {
            unsigned long long a2[4], bd[8];
            #pragma unroll
            for (int i = 0; i < 4; i++)
                a2[i] = *reinterpret_cast<const unsigned long long*>(&As[kk][ty * 8 + 2 * i]);
            #pragma unroll
            for (int j = 0; j < 8; j++)
                bd[j] = BdS[kk][j * 16 + tx];
            #pragma unroll
            for (int i = 0; i < 4; i++)
                #pragma unroll
                for (int j = 0; j < 8; j++)
                    FMA2(acc[i][j], a2[i], bd[j]);
        }
        __syncthreads();
    }

    const int c0 = colBase + tx * 8;
    #pragma unroll
    for (int i = 0; i < 4; i++) {
        #pragma unroll
        for (int h = 0; h < 2; h++) {
            int r = rowBase + ty * 8 + 2 * i + h;
            if (r >= nrows) continue;
            float vals[8];
            #pragma unroll
            for (int j = 0; j < 8; j++) {
                unsigned long long p = acc[i][j];
                unsigned int bits = h ? (unsigned int)(p >> 32) : (unsigned int)p;
                vals[j] = __uint_as_float(bits);
            }
            float* zr = &g_z[(size_t)r * ncols + c0];
            *reinterpret_cast<float4*>(zr)     = make_float4(vals[0], vals[1], vals[2], vals[3]);
            *reinterpret_cast<float4*>(zr + 4) = make_float4(vals[4], vals[5], vals[6], vals[7]);
        }
    }
}

// ---------------- narrow GEMM for layer 3: ncols=40, BN=64 tile, 128 threads ----------------
__global__ __launch_bounds__(128, 4)
void gemm64_kernel(const float* __restrict__ W, int nrows, int ncols)
{
    const float* __restrict__ A = (const float*)g_h;
    __shared__ float As[16][128];
    __shared__ unsigned long long BdS[16][64];

    const int tid = threadIdx.x;
    const int tx = tid & 7, ty = tid >> 3;
    const int rowBase = blockIdx.x * 128;

    const int lr = tid;
    const int arow = rowBase + lr;
    const float sc = (arow < nrows) ? g_isout[arow] : 0.f;

    const int bk  = tid >> 3;
    const int btx = tid & 7;
    const int bc0 = btx * 8;

    unsigned long long acc[4][8];
    #pragma unroll
    for (int i = 0; i < 4; i++)
        #pragma unroll
        for (int j = 0; j < 8; j++) acc[i][j] = 0ull;

    for (int k0 = 0; k0 < 256; k0 += 16) {
        if (arow < nrows) {
            const float4* Ar = reinterpret_cast<const float4*>(A + (size_t)arow * 256);
            #pragma unroll
            for (int q = 0; q < 4; q++) {
                float4 a = Ar[(k0 >> 2) + q];
                As[q * 4 + 0][lr] = a.x * sc;
                As[q * 4 + 1][lr] = a.y * sc;
                As[q * 4 + 2][lr] = a.z * sc;
                As[q * 4 + 3][lr] = a.w * sc;
            }
        } else {
            #pragma unroll
            for (int q = 0; q < 16; q++) As[q][lr] = 0.f;
        }
        float bv[8];
        #pragma unroll
        for (int m = 0; m < 8; m++)
            bv[m] = (bc0 + m < ncols) ? W[(size_t)(k0 + bk) * ncols + bc0 + m] : 0.f;
        #pragma unroll
        for (int m = 0; m < 8; m++) {
            unsigned int b = __float_as_uint(bv[m]);
            BdS[bk][m * 8 + btx] = ((unsigned long long)b << 32) | (unsigned long long)b;
        }
        __syncthreads();

        #pragma unroll
        for (int kk = 0; kk < 16; kk++) {
            unsigned long long a2[4], bd[8];
            #pragma unroll
            for (int i = 0; i < 4; i++)
                a2[i] = *reinterpret_cast<const unsigned long long*>(&As[kk][ty * 8 + 2 * i]);
            #pragma unroll
            for (int j = 0; j < 8; j++)
                bd[j] = BdS[kk][j * 8 + tx];
            #pragma unroll
            for (int i = 0; i < 4; i++)
                #pragma unroll
                for (int j = 0; j < 8; j++)
                    FMA2(acc[i][j], a2[i], bd[j]);
        }
        __syncthreads();
    }

    const int c0 = tx * 8;
    #pragma unroll
    for (int i = 0; i < 4; i++) {
        #pragma unroll
        for (int h = 0; h < 2; h++) {
            int r = rowBase + ty * 8 + 2 * i + h;
            if (r >= nrows) continue;
            #pragma unroll
            for (int j = 0; j < 8; j++) {
                if (c0 + j < ncols) {
                    unsigned long long p = acc[i][j];
                    unsigned int bits = h ? (unsigned int)(p >> 32) : (unsigned int)p;
                    g_z[(size_t)r * ncols + c0 + j] = __uint_as_float(bits);
                }
            }
        }
    }
}

// ---------------- SpMM gather, warp-per-node, feature-split ----------------
// Warp w of each block owns node n = blk*8 + w and 128 dims (half*128..+127).
// Lane accumulates float4 over dims half*128 + lane*4 ..+3.
// Per edge: uniform index load (warp broadcast) + one coalesced warp-LDG.128.
// No shared memory, no __syncthreads.
__global__ __launch_bounds__(256)
void spmm_warp_kernel(const float* __restrict__ bias, int half)
{
    const int warp = threadIdx.x >> 5;
    const int lane = threadIdx.x & 31;
    const int n = blockIdx.x * 8 + warp;
    if (n >= NN) return;
    const int dbase = half * 128 + lane * 4;

    const int beg = g_rowptr[n];
    const int end = g_rowptr[n + 1];
    if (lane == 0 && half == 0) g_fill[n] = 0;   // reset CSR fill counter for next replay

    float4 acc = make_float4(0.f, 0.f, 0.f, 0.f);
    int p = beg;
    for (; p + 4 <= end; p += 4) {
        const int s0 = __ldg(&g_cols[p + 0]);
        const int s1 = __ldg(&g_cols[p + 1]);
        const int s2 = __ldg(&g_cols[p + 2]);
        const int s3 = __ldg(&g_cols[p + 3]);
        const float4 v0 = __ldg((const float4*)(g_z + (size_t)s0 * 256 + dbase));
        const float4 v1 = __ldg((const float4*)(g_z + (size_t)s1 * 256 + dbase));
        const float4 v2 = __ldg((const float4*)(g_z + (size_t)s2 * 256 + dbase));
        const float4 v3 = __ldg((const float4*)(g_z + (size_t)s3 * 256 + dbase));
        acc.x += (v0.x + v1.x) + (v2.x + v3.x);
        acc.y += (v0.y + v1.y) + (v2.y + v3.y);
        acc.z += (v0.z + v1.z) + (v2.z + v3.z);
        acc.w += (v0.w + v1.w) + (v2.w + v3.w);
    }
    for (; p < end; ++p) {
        const int s = __ldg(&g_cols[p]);
        const float4 v = __ldg((const float4*)(g_z + (size_t)s * 256 + dbase));
        acc.x += v.x; acc.y += v.y; acc.z += v.z; acc.w += v.w;
    }

    const float isn = g_isin[n];
    const float4 b4 = *(const float4*)(bias + dbase);
    float4 r;
    r.x = fmaxf(fmaf(acc.x, isn, b4.x), 0.f);
    r.y = fmaxf(fmaf(acc.y, isn, b4.y), 0.f);
    r.z = fmaxf(fmaf(acc.z, isn, b4.z), 0.f);
    r.w = fmaxf(fmaf(acc.w, isn, b4.w), 0.f);
    *(float4*)(g_h + (size_t)n * 256 + dbase) = r;
}

// ---------------- layer-3 SpMM (D=40) fused with log_softmax ----------------
__global__ __launch_bounds__(64)
void spmm_logsoftmax_kernel(const float* __restrict__ bias, float* __restrict__ out)
{
    const int n = blockIdx.x;
    const int d = threadIdx.x;   // 0..63, active d<40
    const int beg = g_rowptr[n];
    const int end = g_rowptr[n + 1];
    float acc = 0.f;
    if (d < DOUT) {
        int p = beg;
        for (; p + 4 <= end; p += 4) {
            float v0 = __ldg(&g_z[(size_t)__ldg(&g_cols[p + 0]) * DOUT + d]);
            float v1 = __ldg(&g_z[(size_t)__ldg(&g_cols[p + 1]) * DOUT + d]);
            float v2 = __ldg(&g_z[(size_t)__ldg(&g_cols[p + 2]) * DOUT + d]);
            float v3 = __ldg(&g_z[(size_t)__ldg(&g_cols[p + 3]) * DOUT + d]);
            acc += (v0 + v1) + (v2 + v3);
        }
        for (; p < end; ++p)
            acc += __ldg(&g_z[(size_t)__ldg(&g_cols[p]) * DOUT + d]);
    }
    float v = (d < DOUT) ? fmaf(acc, g_isin[n], bias[d]) : -INFINITY;

    __shared__ float sm[64];
    sm[d] = v;
    __syncthreads();
    #pragma unroll
    for (int off = 32; off > 0; off >>= 1) {
        if (d < off) sm[d] = fmaxf(sm[d], sm[d + off]);
        __syncthreads();
    }
    float mx = sm[0];
    __syncthreads();
    float ex = (d < DOUT) ? expf(v - mx) : 0.f;
    sm[d] = ex;
    __syncthreads();
    #pragma unroll
    for (int off = 32; off > 0; off >>= 1) {
        if (d < off) sm[d] += sm[d + off];
        __syncthreads();
    }
    float lse = mx + logf(sm[0]);
    if (d < DOUT) out[(size_t)n * DOUT + d] = v - lse;
}

// ---------------- launch ----------------
extern "C" void kernel_launch(void* const* d_in, const int* in_sizes, int n_in,
                              void* d_out, int out_size)
{
    const float* x  = (const float*)d_in[0];
    const float* W1 = (const float*)d_in[1];
    const float* b1 = (const float*)d_in[2];
    const float* W2 = (const float*)d_in[3];
    const float* b2 = (const float*)d_in[4];
    const float* W3 = (const float*)d_in[5];
    const float* b3 = (const float*)d_in[6];
    const int*  src = (const int*)d_in[7];
    const int*  dst = (const int*)d_in[8];
    float* out = (float*)d_out;

    const int nb_e = (EE + 255) / 256;
    const int gm = (NN + 127) / 128;
    const int gw = (NN + 7) / 8;

    // graph prep
    degree_kernel<<<nb_e, 256>>>(src, dst);
    scan_partial_kernel<<<NB_SCAN, 1024>>>();
    scan_mid_kernel<<<1, 32>>>();
    scan_final_kernel<<<NB_SCAN, 1024>>>();   // rowptr + isout/isin + counter reset
    csr_fill_kernel<<<nb_e, 256>>>(src, dst);

    // layer 1: z = (x*isout)@W1 ; h = relu(isin*gather(z) + b1)
    gemm_kernel<<<dim3(2, gm), 256>>>(x, 1, W1, NN, 256);
    spmm_warp_kernel<<<gw, 256>>>(b1, 0);
    spmm_warp_kernel<<<gw, 256>>>(b1, 1);

    // layer 2
    gemm_kernel<<<dim3(2, gm), 256>>>(x, 0, W2, NN, 256);
    spmm_warp_kernel<<<gw, 256>>>(b2, 0);
    spmm_warp_kernel<<<gw, 256>>>(b2, 1);

    // layer 3 (D_OUT=40, narrow tile) + log_softmax
    gemm64_kernel<<<gm, 128>>>(W3, NN, DOUT);
    spmm_logsoftmax_kernel<<<NN, 64>>>(b3, out);
}

// round 12
// speedup vs baseline: 1.2838x; 1.0141x over previous
#include <cuda_runtime.h>
#include <math.h>
#include <stdint.h>

#define NN 100000
#define EE 1600000
#define DHID 256
#define DOUT 40
#define NB_SCAN ((NN + 1023) / 1024)

// ---------------- scratch (device globals; zero-initialized at module load) ----------------
__device__ int   g_outdeg[NN];
__device__ int   g_indeg[NN];
__device__ float g_isout[NN];
__device__ float g_isin[NN];
__device__ int   g_rowptr[NN + 1];
__device__ int   g_fill[NN];
__device__ int   g_bsum[NB_SCAN + 1];
__device__ int   g_cols[EE];
__device__ float g_z[(size_t)NN * DHID];   // GEMM output
__device__ float g_h[(size_t)NN * DHID];   // SpMM output, PRE-SCALED by isout

// Counters (g_outdeg/g_indeg/g_fill) are zeroed AFTER their last use each
// replay (scan_final / spmm), so every replay starts clean.

// ---------------- graph prep ----------------
__global__ void degree_kernel(const int* __restrict__ src, const int* __restrict__ dst) {
    int e = blockIdx.x * blockDim.x + threadIdx.x;
    if (e < EE) {
        atomicAdd(&g_outdeg[src[e]], 1);
        atomicAdd(&g_indeg[dst[e]], 1);
    }
}

__global__ void scan_partial_kernel() {
    __shared__ int ws[32];
    const int b = blockIdx.x, tid = threadIdx.x;
    const int i = b * 1024 + tid;
    int x = (i < NN) ? g_indeg[i] : 0;
    #pragma unroll
    for (int off = 16; off > 0; off >>= 1) x += __shfl_down_sync(0xffffffffu, x, off);
    if ((tid & 31) == 0) ws[tid >> 5] = x;
    __syncthreads();
    if (tid < 32) {
        int w = ws[tid];
        #pragma unroll
        for (int off = 16; off > 0; off >>= 1) w += __shfl_down_sync(0xffffffffu, w, off);
        if (tid == 0) g_bsum[b] = w;
    }
}

__global__ void scan_mid_kernel() {
    if (threadIdx.x == 0) {
        int run = 0;
        for (int b = 0; b < NB_SCAN; b++) { int t = g_bsum[b]; g_bsum[b] = run; run += t; }
        g_rowptr[NN] = run;
    }
}

// rowptr + isout/isin, then zero degree counters for the next replay
__global__ void scan_final_kernel() {
    __shared__ int ws[32];
    const int b = blockIdx.x, tid = threadIdx.x;
    const int lane = tid & 31, wid = tid >> 5;
    const int i = b * 1024 + tid;
    const int v = (i < NN) ? g_indeg[i] : 0;
    int x = v;
    #pragma unroll
    for (int off = 1; off < 32; off <<= 1) {
        int y = __shfl_up_sync(0xffffffffu, x, off);
        if (lane >= off) x += y;
    }
    if (lane == 31) ws[wid] = x;
    __syncthreads();
    if (wid == 0) {
        int w = ws[lane];
        #pragma unroll
        for (int off = 1; off < 32; off <<= 1) {
            int y = __shfl_up_sync(0xffffffffu, w, off);
            if (lane >= off) w += y;
        }
        ws[lane] = w;
    }
    __syncthreads();
    int incl = x + ((wid > 0) ? ws[wid - 1] : 0);
    if (i < NN) {
        g_rowptr[i] = g_bsum[b] + incl - v;
        int od = g_outdeg[i];
        g_isout[i] = (od > 0) ? rsqrtf((float)od) : 0.f;
        g_isin[i]  = (v > 0) ? rsqrtf((float)v) : 0.f;
        g_indeg[i]  = 0;
        g_outdeg[i] = 0;
    }
}

__global__ void csr_fill_kernel(const int* __restrict__ src, const int* __restrict__ dst) {
    int e = blockIdx.x * blockDim.x + threadIdx.x;
    if (e < EE) {
        int d = dst[e];
        int p = g_rowptr[d] + atomicAdd(&g_fill[d], 1);
        g_cols[p] = src[e];
    }
}

// ---------------- GEMM: g_z[r,c] = sum_k A[r,k] * W[k,c]  (NO row scaling) ----------------
// Inputs are pre-scaled (g_h holds h*isout; layer 1's isout is applied at SpMM1 gather).
// Tile 128x128, BK=16, 256 threads, 8x8/thread via packed f32x2 FMA; Bd swizzled.
#define FMA2(d, a, b) asm("fma.rn.f32x2 %0, %1, %2, %0;" : "+l"(d) : "l"(a), "l"(b))

__global__ __launch_bounds__(256, 2)
void gemm_kernel(const float* __restrict__ Xin, int use_x,
                 const float* __restrict__ W, int nrows, int ncols)
{
    const float* __restrict__ A = use_x ? Xin : (const float*)g_h;
    __shared__ float As[16][128];                 // [k][m]
    __shared__ unsigned long long BdS[16][128];   // [k][swizzled pair slot]

    const int tid = threadIdx.x;
    const int tx = tid & 15, ty = tid >> 4;
    const int rowBase = blockIdx.y * 128;
    const int colBase = blockIdx.x * 128;

    const int lr = tid >> 1;
    const int lk = (tid & 1) * 8;
    const int arow = rowBase + lr;

    const int bk  = tid >> 4;
    const int btx = tid & 15;
    const int bc0 = colBase + btx * 8;

    unsigned long long acc[4][8];
    #pragma unroll
    for (int i = 0; i < 4; i++)
        #pragma unroll
        for (int j = 0; j < 8; j++) acc[i][j] = 0ull;

    for (int k0 = 0; k0 < 256; k0 += 16) {
        float4 a0 = make_float4(0.f, 0.f, 0.f, 0.f), a1 = a0;
        if (arow < nrows) {
            const float4* Ar = reinterpret_cast<const float4*>(A + (size_t)arow * 256);
            a0 = Ar[(k0 + lk) >> 2];
            a1 = Ar[(k0 + lk + 4) >> 2];
        }
        As[lk + 0][lr] = a0.x; As[lk + 1][lr] = a0.y;
        As[lk + 2][lr] = a0.z; As[lk + 3][lr] = a0.w;
        As[lk + 4][lr] = a1.x; As[lk + 5][lr] = a1.y;
        As[lk + 6][lr] = a1.z; As[lk + 7][lr] = a1.w;

        float bv[8];
        {
            const float* Wr = &W[(size_t)(k0 + bk) * ncols + bc0];
            float4 w0 = *reinterpret_cast<const float4*>(Wr);
            float4 w1 = *reinterpret_cast<const float4*>(Wr + 4);
            bv[0] = w0.x; bv[1] = w0.y; bv[2] = w0.z; bv[3] = w0.w;
            bv[4] = w1.x; bv[5] = w1.y; bv[6] = w1.z; bv[7] = w1.w;
        }
        #pragma unroll
        for (int m = 0; m < 8; m++) {
            unsigned int b = __float_as_uint(bv[m]);
            unsigned long long pv = ((unsigned long long)b << 32) | (unsigned long long)b;
            BdS[bk][m * 16 + btx] = pv;
        }
        __syncthreads();

        #pragma unroll
        for (int kk = 0; kk < 16; kk++) {
            unsigned long long a2[4], bd[8];
            #pragma unroll
            for (int i = 0; i < 4; i++)
                a2[i] = *reinterpret_cast<const unsigned long long*>(&As[kk][ty * 8 + 2 * i]);
            #pragma unroll
            for (int j = 0; j < 8; j++)
                bd[j] = BdS[kk][j * 16 + tx];
            #pragma unroll
            for (int i = 0; i < 4; i++)
                #pragma unroll
                for (int j = 0; j < 8; j++)
                    FMA2(acc[i][j], a2[i], bd[j]);
        }
        __syncthreads();
    }

    const int c0 = colBase + tx * 8;
    #pragma unroll
    for (int i = 0; i < 4; i++) {
        #pragma unroll
        for (int h = 0; h < 2; h++) {
            int r = rowBase + ty * 8 + 2 * i + h;
            if (r >= nrows) continue;
            float vals[8];
            #pragma unroll
            for (int j = 0; j < 8; j++) {
                unsigned long long p = acc[i][j];
                unsigned int bits = h ? (unsigned int)(p >> 32) : (unsigned int)p;
                vals[j] = __uint_as_float(bits);
            }
            float* zr = &g_z[(size_t)r * ncols + c0];
            *reinterpret_cast<float4*>(zr)     = make_float4(vals[0], vals[1], vals[2], vals[3]);
            *reinterpret_cast<float4*>(zr + 4) = make_float4(vals[4], vals[5], vals[6], vals[7]);
        }
    }
}

// ---------------- narrow GEMM for layer 3: ncols=40, BN=64 tile, 128 threads ----------------
__global__ __launch_bounds__(128, 4)
void gemm64_kernel(const float* __restrict__ W, int nrows, int ncols)
{
    const float* __restrict__ A = (const float*)g_h;
    __shared__ float As[16][128];
    __shared__ unsigned long long BdS[16][64];

    const int tid = threadIdx.x;
    const int tx = tid & 7, ty = tid >> 3;
    const int rowBase = blockIdx.x * 128;

    const int lr = tid;
    const int arow = rowBase + lr;

    const int bk  = tid >> 3;
    const int btx = tid & 7;
    const int bc0 = btx * 8;

    unsigned long long acc[4][8];
    #pragma unroll
    for (int i = 0; i < 4; i++)
        #pragma unroll
        for (int j = 0; j < 8; j++) acc[i][j] = 0ull;

    for (int k0 = 0; k0 < 256; k0 += 16) {
        if (arow < nrows) {
            const float4* Ar = reinterpret_cast<const float4*>(A + (size_t)arow * 256);
            #pragma unroll
            for (int q = 0; q < 4; q++) {
                float4 a = Ar[(k0 >> 2) + q];
                As[q * 4 + 0][lr] = a.x;
                As[q * 4 + 1][lr] = a.y;
                As[q * 4 + 2][lr] = a.z;
                As[q * 4 + 3][lr] = a.w;
            }
        } else {
            #pragma unroll
            for (int q = 0; q < 16; q++) As[q][lr] = 0.f;
        }
        float bv[8];
        #pragma unroll
        for (int m = 0; m < 8; m++)
            bv[m] = (bc0 + m < ncols) ? W[(size_t)(k0 + bk) * ncols + bc0 + m] : 0.f;
        #pragma unroll
        for (int m = 0; m < 8; m++) {
            unsigned int b = __float_as_uint(bv[m]);
            BdS[bk][m * 8 + btx] = ((unsigned long long)b << 32) | (unsigned long long)b;
        }
        __syncthreads();

        #pragma unroll
        for (int kk = 0; kk < 16; kk++) {
            unsigned long long a2[4], bd[8];
            #pragma unroll
            for (int i = 0; i < 4; i++)
                a2[i] = *reinterpret_cast<const unsigned long long*>(&As[kk][ty * 8 + 2 * i]);
            #pragma unroll
            for (int j = 0; j < 8; j++)
                bd[j] = BdS[kk][j * 8 + tx];
            #pragma unroll
            for (int i = 0; i < 4; i++)
                #pragma unroll
                for (int j = 0; j < 8; j++)
                    FMA2(acc[i][j], a2[i], bd[j]);
        }
        __syncthreads();
    }

    const int c0 = tx * 8;
    #pragma unroll
    for (int i = 0; i < 4; i++) {
        #pragma unroll
        for (int h = 0; h < 2; h++) {
            int r = rowBase + ty * 8 + 2 * i + h;
            if (r >= nrows) continue;
            #pragma unroll
            for (int j = 0; j < 8; j++) {
                if (c0 + j < ncols) {
                    unsigned long long p = acc[i][j];
                    unsigned int bits = h ? (unsigned int)(p >> 32) : (unsigned int)p;
                    g_z[(size_t)r * ncols + c0 + j] = __uint_as_float(bits);
                }
            }
        }
    }
}

// ---------------- SpMM gather, warp-per-node, feature-split ----------------
// g_h[n,d] = relu(isin[n]*sum + b[d]) * isout[n]  (pre-scaled for next GEMM).
// gscale: multiply each gathered row by isout[src] (layer 1 only — its GEMM input
// was raw x). Later layers gather plain (inputs already carry isout).
__global__ __launch_bounds__(256)
void spmm_warp_kernel(const float* __restrict__ bias, int half, int gscale)
{
    const int warp = threadIdx.x >> 5;
    const int lane = threadIdx.x & 31;
    const int n = blockIdx.x * 8 + warp;
    if (n >= NN) return;
    const int dbase = half * 128 + lane * 4;

    const int beg = g_rowptr[n];
    const int end = g_rowptr[n + 1];
    if (lane == 0 && half == 0) g_fill[n] = 0;   // reset CSR fill counter for next replay

    float4 acc = make_float4(0.f, 0.f, 0.f, 0.f);
    int p = beg;
    if (gscale) {
        for (; p + 4 <= end; p += 4) {
            const int s0 = __ldg(&g_cols[p + 0]);
            const int s1 = __ldg(&g_cols[p + 1]);
            const int s2 = __ldg(&g_cols[p + 2]);
            const int s3 = __ldg(&g_cols[p + 3]);
            const float o0 = __ldg(&g_isout[s0]);
            const float o1 = __ldg(&g_isout[s1]);
            const float o2 = __ldg(&g_isout[s2]);
            const float o3 = __ldg(&g_isout[s3]);
            const float4 v0 = __ldg((const float4*)(g_z + (size_t)s0 * 256 + dbase));
            const float4 v1 = __ldg((const float4*)(g_z + (size_t)s1 * 256 + dbase));
            const float4 v2 = __ldg((const float4*)(g_z + (size_t)s2 * 256 + dbase));
            const float4 v3 = __ldg((const float4*)(g_z + (size_t)s3 * 256 + dbase));
            acc.x += fmaf(v0.x, o0, fmaf(v1.x, o1, fmaf(v2.x, o2, v3.x * o3)));
            acc.y += fmaf(v0.y, o0, fmaf(v1.y, o1, fmaf(v2.y, o2, v3.y * o3)));
            acc.z += fmaf(v0.z, o0, fmaf(v1.z, o1, fmaf(v2.z, o2, v3.z * o3)));
            acc.w += fmaf(v0.w, o0, fmaf(v1.w, o1, fmaf(v2.w, o2, v3.w * o3)));
        }
        for (; p < end; ++p) {
            const int s = __ldg(&g_cols[p]);
            const float o = __ldg(&g_isout[s]);
            const float4 v = __ldg((const float4*)(g_z + (size_t)s * 256 + dbase));
            acc.x = fmaf(v.x, o, acc.x); acc.y = fmaf(v.y, o, acc.y);
            acc.z = fmaf(v.z, o, acc.z); acc.w = fmaf(v.w, o, acc.w);
        }
    } else {
        for (; p + 4 <= end; p += 4) {
            const int s0 = __ldg(&g_cols[p + 0]);
            const int s1 = __ldg(&g_cols[p + 1]);
            const int s2 = __ldg(&g_cols[p + 2]);
            const int s3 = __ldg(&g_cols[p + 3]);
            const float4 v0 = __ldg((const float4*)(g_z + (size_t)s0 * 256 + dbase));
            const float4 v1 = __ldg((const float4*)(g_z + (size_t)s1 * 256 + dbase));
            const float4 v2 = __ldg((const float4*)(g_z + (size_t)s2 * 256 + dbase));
            const float4 v3 = __ldg((const float4*)(g_z + (size_t)s3 * 256 + dbase));
            acc.x += (v0.x + v1.x) + (v2.x + v3.x);
            acc.y += (v0.y + v1.y) + (v2.y + v3.y);
            acc.z += (v0.z + v1.z) + (v2.z + v3.z);
            acc.w += (v0.w + v1.w) + (v2.w + v3.w);
        }
        for (; p < end; ++p) {
            const int s = __ldg(&g_cols[p]);
            const float4 v = __ldg((const float4*)(g_z + (size_t)s * 256 + dbase));
            acc.x += v.x; acc.y += v.y; acc.z += v.z; acc.w += v.w;
        }
    }

    const float isn = g_isin[n];
    const float osc = g_isout[n];   // pre-scale for next layer's GEMM
    const float4 b4 = *(const float4*)(bias + dbase);
    float4 r;
    r.x = fmaxf(fmaf(acc.x, isn, b4.x), 0.f) * osc;
    r.y = fmaxf(fmaf(acc.y, isn, b4.y), 0.f) * osc;
    r.z = fmaxf(fmaf(acc.z, isn, b4.z), 0.f) * osc;
    r.w = fmaxf(fmaf(acc.w, isn, b4.w), 0.f) * osc;
    *(float4*)(g_h + (size_t)n * 256 + dbase) = r;
}

// ---------------- layer-3 SpMM (D=40, plain gather) fused with log_softmax ----------------
__global__ __launch_bounds__(64)
void spmm_logsoftmax_kernel(const float* __restrict__ bias, float* __restrict__ out)
{
    const int n = blockIdx.x;
    const int d = threadIdx.x;   // 0..63, active d<40
    const int beg = g_rowptr[n];
    const int end = g_rowptr[n + 1];
    float acc = 0.f;
    if (d < DOUT) {
        int p = beg;
        for (; p + 4 <= end; p += 4) {
            float v0 = __ldg(&g_z[(size_t)__ldg(&g_cols[p + 0]) * DOUT + d]);
            float v1 = __ldg(&g_z[(size_t)__ldg(&g_cols[p + 1]) * DOUT + d]);
            float v2 = __ldg(&g_z[(size_t)__ldg(&g_cols[p + 2]) * DOUT + d]);
            float v3 = __ldg(&g_z[(size_t)__ldg(&g_cols[p + 3]) * DOUT + d]);
            acc += (v0 + v1) + (v2 + v3);
        }
        for (; p < end; ++p)
            acc += __ldg(&g_z[(size_t)__ldg(&g_cols[p]) * DOUT + d]);
    }
    float v = (d < DOUT) ? fmaf(acc, g_isin[n], bias[d]) : -INFINITY;

    __shared__ float sm[64];
    sm[d] = v;
    __syncthreads();
    #pragma unroll
    for (int off = 32; off > 0; off >>= 1) {
        if (d < off) sm[d] = fmaxf(sm[d], sm[d + off]);
        __syncthreads();
    }
    float mx = sm[0];
    __syncthreads();
    float ex = (d < DOUT) ? expf(v - mx) : 0.f;
    sm[d] = ex;
    __syncthreads();
    #pragma unroll
    for (int off = 32; off > 0; off >>= 1) {
        if (d < off) sm[d] += sm[d + off];
        __syncthreads();
    }
    float lse = mx + logf(sm[0]);
    if (d < DOUT) out[(size_t)n * DOUT + d] = v - lse;
}

// ---------------- launch ----------------
extern "C" void kernel_launch(void* const* d_in, const int* in_sizes, int n_in,
                              void* d_out, int out_size)
{
    const float* x  = (const float*)d_in[0];
    const float* W1 = (const float*)d_in[1];
    const float* b1 = (const float*)d_in[2];
    const float* W2 = (const float*)d_in[3];
    const float* b2 = (const float*)d_in[4];
    const float* W3 = (const float*)d_in[5];
    const float* b3 = (const float*)d_in[6];
    const int*  src = (const int*)d_in[7];
    const int*  dst = (const int*)d_in[8];
    float* out = (float*)d_out;

    // side stream + fork/join events (created once; resources, not work)
    static cudaStream_t s2 = nullptr;
    static cudaEvent_t ev_fork = nullptr, ev_join = nullptr;
    if (s2 == nullptr) {
        cudaStreamCreateWithFlags(&s2, cudaStreamNonBlocking);
        cudaEventCreateWithFlags(&ev_fork, cudaEventDisableTiming);
        cudaEventCreateWithFlags(&ev_join, cudaEventDisableTiming);
    }

    const int nb_e = (EE + 255) / 256;
    const int gm = (NN + 127) / 128;
    const int gw = (NN + 7) / 8;

    // fork: prep chain on s2, GEMM1 (no graph deps) on main stream
    cudaEventRecord(ev_fork, 0);
    cudaStreamWaitEvent(s2, ev_fork, 0);

    degree_kernel<<<nb_e, 256, 0, s2>>>(src, dst);
    scan_partial_kernel<<<NB_SCAN, 1024, 0, s2>>>();
    scan_mid_kernel<<<1, 32, 0, s2>>>();
    scan_final_kernel<<<NB_SCAN, 1024, 0, s2>>>();
    csr_fill_kernel<<<nb_e, 256, 0, s2>>>(src, dst);
    cudaEventRecord(ev_join, s2);

    gemm_kernel<<<dim3(2, gm), 256>>>(x, 1, W1, NN, 256);   // z1 = x @ W1

    // join: SpMM1 needs both z1 and the graph
    cudaStreamWaitEvent(0, ev_join, 0);

    // layer 1: h1 = relu(isin * sum isout[s]*z1[s] + b1) * isout
    spmm_warp_kernel<<<gw, 256>>>(b1, 0, 1);
    spmm_warp_kernel<<<gw, 256>>>(b1, 1, 1);

    // layer 2: z2 = h1 @ W2 ; h2 = relu(isin * sum z2[s] + b2) * isout
    gemm_kernel<<<dim3(2, gm), 256>>>(x, 0, W2, NN, 256);
    spmm_warp_kernel<<<gw, 256>>>(b2, 0, 0);
    spmm_warp_kernel<<<gw, 256>>>(b2, 1, 0);

    // layer 3: z3 = h2 @ W3 ; out = log_softmax(isin * sum z3[s] + b3)
    gemm64_kernel<<<gm, 128>>>(W3, NN, DOUT);
    spmm_logsoftmax_kernel<<<NN, 64>>>(b3, out);
}